// round 4
// baseline (speedup 1.0000x reference)
#include <cuda_runtime.h>
#include <cuda_bf16.h>
#include <cstdint>
#include <math.h>

#define NT 16384
#define HH 2048
#define NE 64
#define NB 4
#define NS 4096
#define TM 128          // tokens per CTA
#define KT 64           // K elems per tile
#define NTILES (HH/KT)  // 32
#define THREADS 256
#define SMEM_BYTES 98304
#define TAU 1e-4f
#define MAXFIX 4096

// persistent scratch (allocation-free rule: __device__ globals)
__device__ float    g_ssum[NB * NE];
__device__ int      g_cnt[NB * NE];
__device__ uint32_t g_w0[NE * HH / 2];   // bf16x2-packed W plane 0 (hi)
__device__ uint32_t g_w1[NE * HH / 2];   // plane 1 (residual)
__device__ int      g_nfix;
__device__ int      g_fix[MAXFIX];

// ---------------- helpers ----------------
__device__ __forceinline__ uint32_t smem_u32(const void* p) {
    uint32_t a;
    asm("{ .reg .u64 t; cvta.to.shared.u64 t, %1; cvt.u32.u64 %0, t; }" : "=r"(a) : "l"(p));
    return a;
}
// pack two fp32 -> bf16x2 (lo arg -> bits[15:0], hi arg -> bits[31:16])
__device__ __forceinline__ uint32_t pack2(float lo, float hi) {
    uint32_t r;
    asm("cvt.rn.bf16x2.f32 %0, %1, %2;" : "=r"(r) : "f"(hi), "f"(lo));
    return r;
}
__device__ __forceinline__ void ldsm4(uint32_t* r, uint32_t addr) {
    asm volatile("ldmatrix.sync.aligned.m8n8.x4.shared.b16 {%0,%1,%2,%3}, [%4];"
                 : "=r"(r[0]), "=r"(r[1]), "=r"(r[2]), "=r"(r[3]) : "r"(addr));
}
__device__ __forceinline__ void mma16816(float* d, const uint32_t* a, const uint32_t* b) {
    asm volatile("mma.sync.aligned.m16n8k16.row.col.f32.bf16.bf16.f32 "
                 "{%0,%1,%2,%3}, {%4,%5,%6,%7}, {%8,%9}, {%0,%1,%2,%3};"
                 : "+f"(d[0]), "+f"(d[1]), "+f"(d[2]), "+f"(d[3])
                 : "r"(a[0]), "r"(a[1]), "r"(a[2]), "r"(a[3]), "r"(b[0]), "r"(b[1]));
}
// split pair (u,v) into 2 bf16x2 planes (hi + residual)
__device__ __forceinline__ void split2(float u, float v, uint32_t& p0, uint32_t& p1) {
    p0 = pack2(u, v);
    float u0 = __uint_as_float(p0 << 16);
    float v0 = __uint_as_float(p0 & 0xffff0000u);
    p1 = pack2(u - u0, v - v0);
}

// ---------------- W split kernel (+ fixup counter reset) ----------------
__global__ __launch_bounds__(256) void k_wconv(const float* __restrict__ W) {
    if (blockIdx.x == 0 && threadIdx.x == 0) g_nfix = 0;
    int i = (blockIdx.x * 256 + threadIdx.x) * 4;
    float4 v = *(const float4*)(W + i);
    uint32_t a0, a1, b0, b1;
    split2(v.x, v.y, a0, a1);
    split2(v.z, v.w, b0, b1);
    ((uint2*)g_w0)[i >> 2] = make_uint2(a0, b0);
    ((uint2*)g_w1)[i >> 2] = make_uint2(a1, b1);
}

// ---------------- main gate kernel ----------------
__global__ __launch_bounds__(THREADS, 1)
void k_gate(const float* __restrict__ X, float* __restrict__ out, int wbase) {
    extern __shared__ char smem[];
    __shared__ int scnt[NE];
    const int tid  = threadIdx.x;
    const int wid  = tid >> 5;
    const int lane = tid & 31;
    const uint32_t sb = smem_u32(smem);
    const int tokBase = blockIdx.x * TM;

    if (tid < NE) scnt[tid] = 0;

    // smem: A0(s)=sb+s*16384, A1(s)=sb+32768+s*16384, B0(s)=sb+65536+s*8192, B1(s)=sb+81920+s*8192

    // ---- gmem addressing ----
    const int xr = tid >> 4;
    const float* xp = X + (size_t)(tokBase + xr) * HH + (tid & 15) * 4;
    const int wr = tid >> 3;
    const int wc = tid & 7;
    const int wbase4 = wr * 256 + wc;

    // ---- STS swizzled offsets ----
    uint32_t xoff[8], woff[2];
#pragma unroll
    for (int p = 0; p < 8; p++) {
        uint32_t off = (uint32_t)(xr + 16 * p) * 128u + (uint32_t)(tid & 15) * 8u;
        xoff[p] = off ^ ((off >> 3) & 0x70);
    }
#pragma unroll
    for (int q = 0; q < 2; q++) {
        uint32_t off = (uint32_t)(wr + 32 * q) * 128u + (uint32_t)wc * 16u;
        woff[q] = off ^ ((off >> 3) & 0x70);
    }

    // ---- LDSM addressing ----
    const int wm = wid & 3;
    const int wn = wid >> 2;
    const uint32_t xorK  = (uint32_t)(lane & 7);
    const uint32_t kselA = (uint32_t)(lane >> 4);
    const uint32_t kselB = (uint32_t)((lane >> 3) & 1);
    uint32_t rowA[2], rowB[2];
#pragma unroll
    for (int mt = 0; mt < 2; mt++)
        rowA[mt] = (uint32_t)(wm * 32 + mt * 16 + (lane & 15)) * 128u;
    {
        int nB = ((lane >> 4) * 8) + (lane & 7);
#pragma unroll
        for (int pr = 0; pr < 2; pr++)
            rowB[pr] = (uint32_t)(wn * 32 + pr * 16 + nB) * 128u;
    }

    float acc[2][4][4];
#pragma unroll
    for (int mt = 0; mt < 2; mt++)
#pragma unroll
        for (int q = 0; q < 4; q++)
#pragma unroll
            for (int e = 0; e < 4; e++) acc[mt][q][e] = 0.0f;

    // ---- prologue: load tile 0 ----
    float4 xv[8];
    uint4 wv[2][2];
#pragma unroll
    for (int p = 0; p < 8; p++) xv[p] = *(const float4*)(xp + (size_t)p * 16 * HH);
#pragma unroll
    for (int q = 0; q < 2; q++) {
        wv[0][q] = ((const uint4*)g_w0)[wbase4 + q * 8192];
        wv[1][q] = ((const uint4*)g_w1)[wbase4 + q * 8192];
    }

    for (int t = 0; t < NTILES; t++) {
        const int s = t & 1;
        const uint32_t A0 = sb + s * 16384u;
        const uint32_t A1 = A0 + 32768u;
        const uint32_t B0 = sb + 65536u + s * 8192u;
        const uint32_t B1 = B0 + 16384u;

        // convert + STS current tile
#pragma unroll
        for (int p = 0; p < 8; p++) {
            uint32_t p0a, p1a, p0b, p1b;
            split2(xv[p].x, xv[p].y, p0a, p1a);
            split2(xv[p].z, xv[p].w, p0b, p1b);
            asm volatile("st.shared.v2.u32 [%0], {%1,%2};" :: "r"(A0 + xoff[p]), "r"(p0a), "r"(p0b));
            asm volatile("st.shared.v2.u32 [%0], {%1,%2};" :: "r"(A1 + xoff[p]), "r"(p1a), "r"(p1b));
        }
#pragma unroll
        for (int q = 0; q < 2; q++) {
            asm volatile("st.shared.v4.b32 [%0], {%1,%2,%3,%4};"
                         :: "r"(B0 + woff[q]), "r"(wv[0][q].x), "r"(wv[0][q].y), "r"(wv[0][q].z), "r"(wv[0][q].w));
            asm volatile("st.shared.v4.b32 [%0], {%1,%2,%3,%4};"
                         :: "r"(B1 + woff[q]), "r"(wv[1][q].x), "r"(wv[1][q].y), "r"(wv[1][q].z), "r"(wv[1][q].w));
        }

        // prefetch next tile (overlaps sync + MMA)
        if (t + 1 < NTILES) {
            const int tn = t + 1;
#pragma unroll
            for (int p = 0; p < 8; p++)
                xv[p] = *(const float4*)(xp + tn * KT + (size_t)p * 16 * HH);
#pragma unroll
            for (int q = 0; q < 2; q++) {
                wv[0][q] = ((const uint4*)g_w0)[wbase4 + tn * 8 + q * 8192];
                wv[1][q] = ((const uint4*)g_w1)[wbase4 + tn * 8 + q * 8192];
            }
        }

        __syncthreads();

        // ---- ldmatrix + mma ----
#pragma unroll
        for (int ks = 0; ks < 4; ks++) {
            const uint32_t kA = (uint32_t)(2 * ks) + kselA;
            const uint32_t kB = (uint32_t)(2 * ks) + kselB;
            uint32_t bf[2][8];
#pragma unroll
            for (int pr = 0; pr < 2; pr++) {
                ldsm4(&bf[0][pr * 4], B0 + rowB[pr] + ((kB ^ xorK) << 4));
                ldsm4(&bf[1][pr * 4], B1 + rowB[pr] + ((kB ^ xorK) << 4));
            }
            uint32_t af0[2][4], af1[2][4];
            ldsm4(af0[0], A0 + rowA[0] + ((kA ^ xorK) << 4));
            ldsm4(af0[1], A0 + rowA[1] + ((kA ^ xorK) << 4));
            ldsm4(af1[0], A1 + rowA[0] + ((kA ^ xorK) << 4));
            ldsm4(af1[1], A1 + rowA[1] + ((kA ^ xorK) << 4));
#pragma unroll
            for (int mt = 0; mt < 2; mt++)
#pragma unroll
                for (int q = 0; q < 4; q++) {
                    mma16816(acc[mt][q], af0[mt], &bf[0][q * 2]);   // x0*w0
                    mma16816(acc[mt][q], af0[mt], &bf[1][q * 2]);   // x0*w1
                    mma16816(acc[mt][q], af1[mt], &bf[0][q * 2]);   // x1*w0
                }
        }
    }

    __syncthreads();   // buffers free; reuse as logits

    // ---- accumulators -> logits smem [128][66] ----
    float* Lg = (float*)smem;
    {
        const int g  = lane >> 2;
        const int tg = lane & 3;
#pragma unroll
        for (int mt = 0; mt < 2; mt++)
#pragma unroll
            for (int q = 0; q < 4; q++) {
                int m0 = wm * 32 + mt * 16 + g;
                int c  = wn * 32 + q * 8 + tg * 2;
                Lg[m0 * 66 + c]           = acc[mt][q][0];
                Lg[m0 * 66 + c + 1]       = acc[mt][q][1];
                Lg[(m0 + 8) * 66 + c]     = acc[mt][q][2];
                Lg[(m0 + 8) * 66 + c + 1] = acc[mt][q][3];
            }
    }
    __syncthreads();

    // ---- per-token softmax / top-2 (+ near-tie flagging) ----
    if (tid < TM) {
        float v[64];
#pragma unroll
        for (int e = 0; e < NE; e++) v[e] = Lg[tid * 66 + e];

        float m = -1e30f;
#pragma unroll
        for (int e = 0; e < NE; e++) m = fmaxf(m, v[e]);

        float Z = 0.0f, b1 = -1e30f, b2 = -1e30f, b3 = -1e30f;
        int i1 = 0, i2 = 0, i3 = 0;
#pragma unroll
        for (int e = 0; e < NE; e++) {
            float x = v[e];
            float ex = __expf(x - m);
            v[e] = ex;
            Z += ex;
            if (x > b1)      { b3 = b2; i3 = i2; b2 = b1; i2 = i1; b1 = x; i1 = e; }
            else if (x > b2) { b3 = b2; i3 = i2; b2 = x;  i2 = e; }
            else if (x > b3) { b3 = x;  i3 = e; }
        }
        float invZ = 1.0f / Z;
        float s1 = v[i1] * invZ;
        float s2 = v[i2] * invZ;
        float den = s1 + s2 + 1e-20f;

        int gt = tokBase + tid;
        out[gt * 2 + 0] = (float)i1;
        out[gt * 2 + 1] = (float)i2;
        out[wbase + gt * 2 + 0] = s1 / den;
        out[wbase + gt * 2 + 1] = s2 / den;

        if ((b1 - b2 < TAU) || (b2 - b3 < TAU)) {
            int slot = atomicAdd(&g_nfix, 1);
            if (slot < MAXFIX) g_fix[slot] = gt;
        }

        atomicAdd(&scnt[i1], 1);
        atomicAdd(&scnt[i2], 1);

#pragma unroll
        for (int e = 0; e < NE; e++) Lg[tid * 66 + e] = v[e] * invZ;
    }
    __syncthreads();

    if (tid < NE) {
        float ssum = 0.0f;
        for (int r = 0; r < TM; r++) ssum += Lg[r * 66 + tid];
        const int b = tokBase >> 12;
        atomicAdd(&g_ssum[b * NE + tid], ssum);
        int c = scnt[tid];
        if (c) atomicAdd(&g_cnt[b * NE + tid], c);
    }
}

// ---------------- fp64 fixup for near-tie tokens ----------------
__global__ __launch_bounds__(256) void k_fixup(const float* __restrict__ X,
                                               const float* __restrict__ W,
                                               float* __restrict__ out, int wbase) {
    __shared__ double part[256];
    __shared__ double lg[64];
    int n = g_nfix;
    if (n > MAXFIX) n = MAXFIX;
    const int tid = threadIdx.x;
    const int e = tid & 63;
    const int j = tid >> 6;

    for (int s = blockIdx.x; s < n; s += gridDim.x) {
        int gt = g_fix[s];
        const float* xr = X + (size_t)gt * HH;
        const float* wr = W + (size_t)e * HH;
        double a0 = 0.0, a1 = 0.0, a2 = 0.0, a3 = 0.0;
        int k0 = j * 512;
#pragma unroll 4
        for (int k = k0; k < k0 + 512; k += 4) {
            a0 += (double)xr[k + 0] * (double)wr[k + 0];
            a1 += (double)xr[k + 1] * (double)wr[k + 1];
            a2 += (double)xr[k + 2] * (double)wr[k + 2];
            a3 += (double)xr[k + 3] * (double)wr[k + 3];
        }
        part[tid] = (a0 + a1) + (a2 + a3);
        __syncthreads();
        if (tid < 64) lg[e] = part[e] + part[e + 64] + part[e + 128] + part[e + 192];
        __syncthreads();
        if (tid == 0) {
            double m = -1e300;
            for (int q = 0; q < 64; q++) if (lg[q] > m) m = lg[q];
            double Z = 0.0, b1 = -1e300, b2 = -1e300;
            int i1 = 0, i2 = 0;
            for (int q = 0; q < 64; q++) {
                double x = lg[q];
                Z += exp(x - m);
                if (x > b1)      { b2 = b1; i2 = i1; b1 = x; i1 = q; }
                else if (x > b2) { b2 = x;  i2 = q; }
            }
            double s1 = exp(b1 - m) / Z;
            double s2 = exp(b2 - m) / Z;
            double den = s1 + s2 + 1e-20;

            int o1 = (int)out[gt * 2 + 0];
            int o2 = (int)out[gt * 2 + 1];
            const int b = gt >> 12;
            if (o1 != i1) { atomicAdd(&g_cnt[b * NE + o1], -1); atomicAdd(&g_cnt[b * NE + i1], 1); }
            if (o2 != i2) { atomicAdd(&g_cnt[b * NE + o2], -1); atomicAdd(&g_cnt[b * NE + i2], 1); }

            out[gt * 2 + 0] = (float)i1;
            out[gt * 2 + 1] = (float)i2;
            out[wbase + gt * 2 + 0] = (float)(s1 / den);
            out[wbase + gt * 2 + 1] = (float)(s2 / den);
        }
        __syncthreads();
    }
}

// ---------------- aux loss + scratch reset ----------------
__global__ void k_aux(float* __restrict__ out, int aux_idx) {
    __shared__ float red[NB * NE];
    int i = threadIdx.x;
    float v = (float)g_cnt[i] * ((float)NE / (float)(NS * 2)) * (g_ssum[i] / (float)NS);
    red[i] = v;
    g_cnt[i] = 0;       // reset for next graph replay
    g_ssum[i] = 0.0f;
    __syncthreads();
    for (int s = 128; s > 0; s >>= 1) {
        if (i < s) red[i] += red[i + s];
        __syncthreads();
    }
    if (i == 0) out[aux_idx] = red[0] / (float)NB * 0.1f;
}

extern "C" void kernel_launch(void* const* d_in, const int* in_sizes, int n_in,
                              void* d_out, int out_size) {
    const float* X = (const float*)d_in[0];   // [4,4096,2048] fp32
    const float* W = (const float*)d_in[1];   // [64,2048] fp32
    float* out = (float*)d_out;
    const int wbase = (out_size - 1) / 2;     // 32768

    cudaFuncSetAttribute(k_gate, cudaFuncAttributeMaxDynamicSharedMemorySize, SMEM_BYTES);

    k_wconv<<<128, 256>>>(W);
    k_gate<<<NT / TM, THREADS, SMEM_BYTES>>>(X, out, wbase);
    k_fixup<<<64, 256>>>(X, W, out, wbase);
    k_aux<<<1, NB * NE>>>(out, out_size - 1);
}

// round 5
// speedup vs baseline: 1.5948x; 1.5948x over previous
#include <cuda_runtime.h>
#include <cstdint>
#include <math.h>

#define NT 16384
#define HH 2048
#define NE 64
#define NB 4
#define NS 4096
#define TM 128          // tokens per CTA
#define KC 32           // K elems per tile
#define NTILES (HH/KC)  // 64
#define THREADS 256
#define SMEM_BYTES 49664

// persistent scratch (allocation-free rule: __device__ globals)
__device__ float g_ssum[NB * NE];
__device__ int   g_cnt[NB * NE];

// ---------------- helpers ----------------
__device__ __forceinline__ uint32_t smem_u32(const void* p) {
    uint32_t a;
    asm("{ .reg .u64 t; cvta.to.shared.u64 t, %1; cvt.u32.u64 %0, t; }" : "=r"(a) : "l"(p));
    return a;
}
#define FMA2(acc, a2, b2) \
    asm("fma.rn.f32x2 %0, %1, %2, %0;" : "+l"(acc) : "l"(a2), "l"(b2))
#define DUP2(d, s) \
    asm("mov.b64 %0, {%1, %1};" : "=l"(d) : "r"(s))

// ---------------- main gate kernel ----------------
__global__ __launch_bounds__(THREADS, 1)
void k_gate(const float* __restrict__ X, const float* __restrict__ W,
            float* __restrict__ out, int wbase) {
    extern __shared__ char smem[];
    const int tid  = threadIdx.x;
    const int wid  = tid >> 5;          // expert group: experts wid*8 .. wid*8+7
    const int lane = tid & 31;          // token group:  tokens lane*4 .. lane*4+3
    const uint32_t sb = smem_u32(smem);
    const int tokBase = blockIdx.x * TM;

    int* scnt = (int*)(smem + 49152);
    if (tid < NE) scnt[tid] = 0;

    // smem: xs[s][32][128] fp32 at sb + s*16384 ; ws[s][32][64] at sb + 32768 + s*8192
    const uint32_t XS0 = sb;
    const uint32_t WS0 = sb + 32768u;

    // ---- gmem load mapping ----
    // X: tok = tid>>1 (0..127), qsel = tid&1; quads q = qsel*4 + p (p=0..3)
    const int xtok  = tid >> 1;
    const int xqsel = tid & 1;
    const float* xp = X + (size_t)(tokBase + xtok) * HH + xqsel * 16;
    // W: e = tid&63, q2 = tid>>6; quads q = q2 + 4p (p=0..1)
    const int we  = tid & 63;
    const int wq2 = tid >> 6;
    const float* wp = W + (size_t)we * HH + wq2 * 4;

    // STS base offsets (bytes): xs[k][tok] k-major, row 512B; ws[k][e], row 256B
    // X STS: row k = q*4+j -> addr = (q*4+j)*512 + xtok*4
    // W STS: row k = q*4+j -> addr = (q*4+j)*256 + we*4

    // accumulators: acc2[i][ep] : token lane*4+i, expert pair wid*8 + ep*2 {+0,+1}
    unsigned long long acc2[4][4];
#pragma unroll
    for (int i = 0; i < 4; i++)
#pragma unroll
        for (int ep = 0; ep < 4; ep++) acc2[i][ep] = 0ull;

    // ---- prologue: load tile 0 into regs ----
    float4 xv[4];
    float4 wv[2];
#pragma unroll
    for (int p = 0; p < 4; p++) xv[p] = *(const float4*)(xp + p * 4);
#pragma unroll
    for (int p = 0; p < 2; p++) wv[p] = *(const float4*)(wp + p * 16);

    const uint32_t aAddrBase = (uint32_t)lane * 16u;   // lane*4 floats
    const uint32_t bAddrBase = (uint32_t)wid * 32u;    // eg*8 floats

    for (int t = 0; t < NTILES; t++) {
        const int s = t & 1;
        const uint32_t xsb = XS0 + (uint32_t)s * 16384u;
        const uint32_t wsb = WS0 + (uint32_t)s * 8192u;

        // ---- STS tile t (transpose to k-major) ----
#pragma unroll
        for (int p = 0; p < 4; p++) {
            const uint32_t kq = (uint32_t)(xqsel * 4 + p);
            const uint32_t a0 = xsb + kq * 4u * 512u + (uint32_t)xtok * 4u;
            asm volatile("st.shared.f32 [%0], %1;"       :: "r"(a0),          "f"(xv[p].x));
            asm volatile("st.shared.f32 [%0], %1;"       :: "r"(a0 + 512u),   "f"(xv[p].y));
            asm volatile("st.shared.f32 [%0], %1;"       :: "r"(a0 + 1024u),  "f"(xv[p].z));
            asm volatile("st.shared.f32 [%0], %1;"       :: "r"(a0 + 1536u),  "f"(xv[p].w));
        }
#pragma unroll
        for (int p = 0; p < 2; p++) {
            const uint32_t kq = (uint32_t)(wq2 + 4 * p);
            const uint32_t a0 = wsb + kq * 4u * 256u + (uint32_t)we * 4u;
            asm volatile("st.shared.f32 [%0], %1;"       :: "r"(a0),          "f"(wv[p].x));
            asm volatile("st.shared.f32 [%0], %1;"       :: "r"(a0 + 256u),   "f"(wv[p].y));
            asm volatile("st.shared.f32 [%0], %1;"       :: "r"(a0 + 512u),   "f"(wv[p].z));
            asm volatile("st.shared.f32 [%0], %1;"       :: "r"(a0 + 768u),   "f"(wv[p].w));
        }

        __syncthreads();

        // ---- prefetch tile t+1 into regs (in flight during FMA phase) ----
        if (t + 1 < NTILES) {
            const int k0 = (t + 1) * KC;
#pragma unroll
            for (int p = 0; p < 4; p++) xv[p] = *(const float4*)(xp + k0 + p * 4);
#pragma unroll
            for (int p = 0; p < 2; p++) wv[p] = *(const float4*)(wp + k0 + p * 16);
        }

        // ---- FMA phase over buf s ----
        const uint32_t aB = xsb + aAddrBase;
        const uint32_t bB = wsb + bAddrBase;
#pragma unroll
        for (int k = 0; k < KC; k++) {
            float a0, a1, a2, a3;
            asm("ld.shared.v4.f32 {%0,%1,%2,%3}, [%4];"
                : "=f"(a0), "=f"(a1), "=f"(a2), "=f"(a3)
                : "r"(aB + (uint32_t)k * 512u));
            unsigned long long b01, b23, b45, b67;
            asm("ld.shared.v2.u64 {%0,%1}, [%2];"
                : "=l"(b01), "=l"(b23) : "r"(bB + (uint32_t)k * 256u));
            asm("ld.shared.v2.u64 {%0,%1}, [%2];"
                : "=l"(b45), "=l"(b67) : "r"(bB + (uint32_t)k * 256u + 16u));

            unsigned long long ad0, ad1, ad2, ad3;
            DUP2(ad0, __float_as_uint(a0));
            DUP2(ad1, __float_as_uint(a1));
            DUP2(ad2, __float_as_uint(a2));
            DUP2(ad3, __float_as_uint(a3));

            FMA2(acc2[0][0], ad0, b01); FMA2(acc2[0][1], ad0, b23);
            FMA2(acc2[0][2], ad0, b45); FMA2(acc2[0][3], ad0, b67);
            FMA2(acc2[1][0], ad1, b01); FMA2(acc2[1][1], ad1, b23);
            FMA2(acc2[1][2], ad1, b45); FMA2(acc2[1][3], ad1, b67);
            FMA2(acc2[2][0], ad2, b01); FMA2(acc2[2][1], ad2, b23);
            FMA2(acc2[2][2], ad2, b45); FMA2(acc2[2][3], ad2, b67);
            FMA2(acc2[3][0], ad3, b01); FMA2(acc2[3][1], ad3, b23);
            FMA2(acc2[3][2], ad3, b45); FMA2(acc2[3][3], ad3, b67);
        }
        __syncthreads();
    }

    // ---- accumulators -> logits smem [128][66] ----
    float* Lg = (float*)smem;
#pragma unroll
    for (int i = 0; i < 4; i++) {
        const int tok = lane * 4 + i;
#pragma unroll
        for (int ep = 0; ep < 4; ep++) {
            uint32_t lo, hi;
            asm("mov.b64 {%0,%1}, %2;" : "=r"(lo), "=r"(hi) : "l"(acc2[i][ep]));
            const int e = wid * 8 + ep * 2;
            asm volatile("st.shared.v2.f32 [%0], {%1,%2};"
                         :: "r"(sb + (uint32_t)(tok * 66 + e) * 4u),
                            "f"(__uint_as_float(lo)), "f"(__uint_as_float(hi)));
        }
    }
    __syncthreads();

    // ---- per-token softmax / top-2 ----
    if (tid < TM) {
        float v[64];
#pragma unroll
        for (int e = 0; e < NE; e++) v[e] = Lg[tid * 66 + e];

        float m = -1e30f;
#pragma unroll
        for (int e = 0; e < NE; e++) m = fmaxf(m, v[e]);

        float Z = 0.0f, b1 = -1e30f, b2 = -1e30f;
        int i1 = 0, i2 = 0;
#pragma unroll
        for (int e = 0; e < NE; e++) {
            float x = v[e];
            float ex = __expf(x - m);
            v[e] = ex;
            Z += ex;
            if (x > b1)      { b2 = b1; i2 = i1; b1 = x; i1 = e; }
            else if (x > b2) { b2 = x;  i2 = e; }
        }
        float invZ = 1.0f / Z;
        float s1 = v[i1] * invZ;
        float s2 = v[i2] * invZ;
        float den = s1 + s2 + 1e-20f;

        int gt = tokBase + tid;
        out[gt * 2 + 0] = (float)i1;
        out[gt * 2 + 1] = (float)i2;
        out[wbase + gt * 2 + 0] = s1 / den;
        out[wbase + gt * 2 + 1] = s2 / den;

        atomicAdd(&scnt[i1], 1);
        atomicAdd(&scnt[i2], 1);

#pragma unroll
        for (int e = 0; e < NE; e++) Lg[tid * 66 + e] = v[e] * invZ;
    }
    __syncthreads();

    if (tid < NE) {
        float ssum = 0.0f;
        for (int r = 0; r < TM; r++) ssum += Lg[r * 66 + tid];
        const int b = tokBase >> 12;
        atomicAdd(&g_ssum[b * NE + tid], ssum);
        int c = scnt[tid];
        if (c) atomicAdd(&g_cnt[b * NE + tid], c);
    }
}

// ---------------- aux loss + scratch reset ----------------
__global__ void k_aux(float* __restrict__ out, int aux_idx) {
    __shared__ float red[NB * NE];
    int i = threadIdx.x;
    float v = (float)g_cnt[i] * ((float)NE / (float)(NS * 2)) * (g_ssum[i] / (float)NS);
    red[i] = v;
    g_cnt[i] = 0;       // reset for next graph replay
    g_ssum[i] = 0.0f;
    __syncthreads();
    for (int s = 128; s > 0; s >>= 1) {
        if (i < s) red[i] += red[i + s];
        __syncthreads();
    }
    if (i == 0) out[aux_idx] = red[0] / (float)NB * 0.1f;
}

extern "C" void kernel_launch(void* const* d_in, const int* in_sizes, int n_in,
                              void* d_out, int out_size) {
    const float* X = (const float*)d_in[0];   // [4,4096,2048] fp32
    const float* W = (const float*)d_in[1];   // [64,2048] fp32
    float* out = (float*)d_out;
    const int wbase = (out_size - 1) / 2;     // 32768

    cudaFuncSetAttribute(k_gate, cudaFuncAttributeMaxDynamicSharedMemorySize, SMEM_BYTES);

    k_gate<<<NT / TM, THREADS, SMEM_BYTES>>>(X, W, out, wbase);
    k_aux<<<1, NB * NE>>>(out, out_size - 1);
}